// round 14
// baseline (speedup 1.0000x reference)
#include <cuda_runtime.h>
#include <cstdint>
#include <math.h>

#define N_TOK   8192
#define D_DIM   4096
#define E_NUM   8
#define R_RANK  128
#define SCALING 0.25f
#define MT      64

__device__ int   g_cnt[2][E_NUM];
__device__ int   g_tok[2][E_NUM][N_TOK];
__device__ float g_wt [2][E_NUM][N_TOK];
// gate-weighted, tf32-rounded H for every (slot, expert, list-position)
__device__ float g_h[2][E_NUM][N_TOK][R_RANK];   // 64 MB reserved, 8 MB live

// ---- stage-1 smem (KB=64): X[64][68w] x2 + A[128][68w] x2 = 104448 B -> 2 CTAs/SM
#define S1_X(b) ((b) * 17408)
#define S1_A(b) (34816 + (b) * 34816)
#define SMEM_S1 104448
// ---- stage-2 smem (101376 B -> 2 CTAs/SM) ----
#define S2_H    0                          // H [64][132w]
#define S2_B    33792                      // B [128][132w] single buffer
#define SMEM_S2 101376

__device__ __forceinline__ uint32_t smem_u32(const void* p) {
    uint32_t a;
    asm("{ .reg .u64 t; cvta.to.shared.u64 t, %1; cvt.u32.u64 %0, t; }" : "=r"(a) : "l"(p));
    return a;
}
__device__ __forceinline__ uint32_t cvt_tf32(float f) {
    uint32_t r; asm("cvt.rna.tf32.f32 %0, %1;" : "=r"(r) : "f"(f)); return r;
}
#define CP16(sa, gp) asm volatile("cp.async.cg.shared.global [%0], [%1], 16;" :: "r"(sa), "l"(gp))
#define CPCOMMIT()   asm volatile("cp.async.commit_group;" ::: "memory")
#define CPWAIT(n)    asm volatile("cp.async.wait_group %0;" :: "n"(n) : "memory")

__device__ __forceinline__ void mma8(float* c, const uint32_t* a, const uint32_t* b) {
    asm volatile("mma.sync.aligned.m16n8k8.row.col.f32.tf32.tf32.f32 "
        "{%0,%1,%2,%3}, {%4,%5,%6,%7}, {%8,%9}, {%0,%1,%2,%3};"
        : "+f"(c[0]), "+f"(c[1]), "+f"(c[2]), "+f"(c[3])
        : "r"(a[0]), "r"(a[1]), "r"(a[2]), "r"(a[3]), "r"(b[0]), "r"(b[1]));
}

// ---------------- kernels ----------------
__global__ void reset_kernel() {
    if (threadIdx.x < 2 * E_NUM) ((int*)g_cnt)[threadIdx.x] = 0;
}

// Router v4: 4 tokens/block.
__global__ __launch_bounds__(256) void router_kernel(
    const float* __restrict__ x, const float* __restrict__ Wr, const float* __restrict__ br)
{
    const int n0 = blockIdx.x * 4, tid = threadIdx.x;
    const int warp = tid >> 5, lane = tid & 31;
    float acc[4][E_NUM];
#pragma unroll
    for (int t = 0; t < 4; t++)
#pragma unroll
        for (int e = 0; e < E_NUM; e++) acc[t][e] = 0.f;
    for (int d = tid * 4; d < D_DIM; d += 1024) {
        float4 wv[E_NUM];
#pragma unroll
        for (int e = 0; e < E_NUM; e++) wv[e] = *(const float4*)(Wr + (size_t)e * D_DIM + d);
#pragma unroll
        for (int t = 0; t < 4; t++) {
            float4 xv = *(const float4*)(x + (size_t)(n0 + t) * D_DIM + d);
#pragma unroll
            for (int e = 0; e < E_NUM; e++)
                acc[t][e] += xv.x*wv[e].x + xv.y*wv[e].y + xv.z*wv[e].z + xv.w*wv[e].w;
        }
    }
#pragma unroll
    for (int off = 16; off > 0; off >>= 1)
#pragma unroll
        for (int t = 0; t < 4; t++)
#pragma unroll
            for (int e = 0; e < E_NUM; e++)
                acc[t][e] += __shfl_xor_sync(0xffffffffu, acc[t][e], off);
    __shared__ float sm[8][4][E_NUM];
    if (lane == 0)
#pragma unroll
        for (int t = 0; t < 4; t++)
#pragma unroll
            for (int e = 0; e < E_NUM; e++) sm[warp][t][e] = acc[t][e];
    __syncthreads();
    if (tid < 4) {
        const int n = n0 + tid;
        float lg[E_NUM];
#pragma unroll
        for (int e = 0; e < E_NUM; e++) {
            float s = 0.f;
#pragma unroll
            for (int w = 0; w < 8; w++) s += sm[w][tid][e];
            lg[e] = s + br[e];
        }
        int i0 = 0;
#pragma unroll
        for (int e = 1; e < E_NUM; e++) if (lg[e] > lg[i0]) i0 = e;
        int i1 = (i0 == 0) ? 1 : 0;
#pragma unroll
        for (int e = 0; e < E_NUM; e++) if (e != i0 && lg[e] > lg[i1]) i1 = e;
        float e1  = expf(lg[i1] - lg[i0]);
        float inv = SCALING / (1.f + e1);
        int p0 = atomicAdd(&g_cnt[0][i0], 1);
        g_tok[0][i0][p0] = n;  g_wt[0][i0][p0] = inv;
        int p1 = atomicAdd(&g_cnt[1][i1], 1);
        g_tok[1][i1][p1] = n;  g_wt[1][i1][p1] = e1 * inv;
    }
}

// Stage 1 (both slots in one launch, 256 active blocks, 2 CTAs/SM, KB=64):
// H[slot][e][base+r][:] = gate * (X_g @ A_e^T), tf32-rounded.
__global__ __launch_bounds__(256, 2)
void s1_kernel(const float* __restrict__ x, const float* __restrict__ A)
{
    const int slot = blockIdx.z, e = blockIdx.y;
    const int cnt  = g_cnt[slot][e];
    const int base = blockIdx.x * MT;
    if (base >= cnt) return;

    extern __shared__ char dsm[];
    __shared__ int   stok[MT];
    __shared__ float swt[MT];

    const int tid  = threadIdx.x;
    const int lane = tid & 31, warp = tid >> 5;
    const int wm = warp >> 2, wn = warp & 3;
    const int lm = lane >> 2, lk = lane & 3;

    if (tid < MT) {
        int p = base + tid;
        if (p < cnt) { stok[tid] = g_tok[slot][e][p];    swt[tid] = g_wt[slot][e][p]; }
        else         { stok[tid] = g_tok[slot][e][base]; swt[tid] = 0.f;              }
    }
    __syncthreads();

    const uint32_t sb = smem_u32(dsm);
    // X: 64 rows, 4 thr/row; 4 CP16 each -> cols q*16 + j*4; stride 272 B
    const int xr_ = tid >> 2, xq_ = tid & 3;
    const float* xg = x + (size_t)stok[xr_] * D_DIM + xq_ * 16;
    const uint32_t xo = (uint32_t)xr_ * 272u + (uint32_t)xq_ * 64u;
    // A: 128 rows, 2 thr/row; 8 CP16 each -> cols q*32 + j*4; stride 272 B
    const int ar_ = tid >> 1, aq_ = tid & 1;
    const float* ag = A + ((size_t)e * R_RANK + ar_) * D_DIM + aq_ * 32;
    const uint32_t ao = (uint32_t)ar_ * 272u + (uint32_t)aq_ * 128u;

    float c[2][4][4];
#pragma unroll
    for (int mt = 0; mt < 2; mt++)
#pragma unroll
        for (int nt = 0; nt < 4; nt++)
#pragma unroll
            for (int q = 0; q < 4; q++) c[mt][nt][q] = 0.f;

    {
#pragma unroll
        for (int j = 0; j < 4; j++) CP16(sb + S1_X(0) + xo + j * 16u, xg + j * 4);
#pragma unroll
        for (int j = 0; j < 8; j++) CP16(sb + S1_A(0) + ao + j * 16u, ag + j * 4);
        CPCOMMIT();
    }
    for (int kt = 0; kt < 64; kt++) {
        if (kt + 1 < 64) {
            const int b = (kt + 1) & 1, gk = (kt + 1) * 64;
#pragma unroll
            for (int j = 0; j < 4; j++) CP16(sb + S1_X(b) + xo + j * 16u, xg + gk + j * 4);
#pragma unroll
            for (int j = 0; j < 8; j++) CP16(sb + S1_A(b) + ao + j * 16u, ag + gk + j * 4);
            CPCOMMIT();
            CPWAIT(1);
        } else {
            CPWAIT(0);
        }
        __syncthreads();
        const float* Xs = (const float*)(dsm + S1_X(kt & 1));
        const float* As = (const float*)(dsm + S1_A(kt & 1));
#pragma unroll
        for (int ks = 0; ks < 8; ks++) {
            const int k0 = ks * 8 + lk;
            uint32_t af[2][4], bf[4][2];
#pragma unroll
            for (int mt = 0; mt < 2; mt++) {
                const int r0 = wm * 32 + mt * 16 + lm;
                af[mt][0] = cvt_tf32(Xs[r0 * 68 + k0]);
                af[mt][1] = cvt_tf32(Xs[(r0 + 8) * 68 + k0]);
                af[mt][2] = cvt_tf32(Xs[r0 * 68 + k0 + 4]);
                af[mt][3] = cvt_tf32(Xs[(r0 + 8) * 68 + k0 + 4]);
            }
#pragma unroll
            for (int nt = 0; nt < 4; nt++) {
                const int n0 = wn * 32 + nt * 8 + lm;
                bf[nt][0] = cvt_tf32(As[n0 * 68 + k0]);
                bf[nt][1] = cvt_tf32(As[n0 * 68 + k0 + 4]);
            }
#pragma unroll
            for (int mt = 0; mt < 2; mt++)
#pragma unroll
                for (int nt = 0; nt < 4; nt++) mma8(c[mt][nt], af[mt], bf[nt]);
        }
        __syncthreads();
    }

    // H epilogue: gate-weight + tf32 -> gmem (L2-resident, 8 MB live)
#pragma unroll
    for (int mt = 0; mt < 2; mt++)
#pragma unroll
        for (int h = 0; h < 2; h++) {
            const int r = wm * 32 + mt * 16 + lm + h * 8;
            const float w = swt[r];
            uint32_t* hp = (uint32_t*)&g_h[slot][e][base + r][0];
#pragma unroll
            for (int nt = 0; nt < 4; nt++) {
                const int col = wn * 32 + nt * 8 + lk * 2;
                uint2 v;
                v.x = cvt_tf32(c[mt][nt][h * 2]     * w);
                v.y = cvt_tf32(c[mt][nt][h * 2 + 1] * w);
                *(uint2*)&hp[col] = v;
            }
        }
}

// Stage 2: out (+)= H @ B_e^T. Grid (tiles, nhalf, expert); 16 N-chunks/block.
__global__ __launch_bounds__(256, 2)
void s2_kernel(const float* __restrict__ B, float* __restrict__ out, int slot)
{
    const int e    = blockIdx.z;
    const int nh   = blockIdx.y;
    const int cnt  = g_cnt[slot][e];
    const int base = blockIdx.x * MT;
    if (base >= cnt) return;

    extern __shared__ char dsm[];
    __shared__ int stok[MT];

    const int tid  = threadIdx.x;
    const int lane = tid & 31, warp = tid >> 5;
    const int wm = warp >> 2, wn = warp & 3;
    const int lm = lane >> 2, lk = lane & 3;

    if (tid < MT) {
        int p = base + tid;
        stok[tid] = (p < cnt) ? g_tok[slot][e][p] : g_tok[slot][e][base];
    }
    __syncthreads();

    const uint32_t sb = smem_u32(dsm);

    // H load: 8 CP16/thread; row = tid>>2, q = tid&3 -> cols q*32 + j*4
    const int hr = tid >> 2, hq = tid & 3;
    const float* hg = &g_h[slot][e][base + hr][hq * 32];
    const uint32_t ho = (uint32_t)hr * 528u + (uint32_t)hq * 128u;
#pragma unroll
    for (int j = 0; j < 8; j++)
        CP16(sb + S2_H + ho + j * 16u, hg + j * 4);
    CPCOMMIT();

    // B loader: rows warp + 8j, col16 = lane; chunk ch covers d-rows (nh*16+ch)*128
    const float* bg = B + (size_t)e * D_DIM * R_RANK
                        + ((size_t)nh * 16 * 128 + warp) * R_RANK + lane * 4;
    const uint32_t bo = (uint32_t)warp * 528u + (uint32_t)lane * 16u;
#pragma unroll
    for (int j = 0; j < 16; j++)
        CP16(sb + S2_B + bo + j * 4224u, bg + (size_t)j * 8 * R_RANK);
    CPCOMMIT();

    int tk[2][2]; bool vv[2][2];
#pragma unroll
    for (int mt = 0; mt < 2; mt++)
#pragma unroll
        for (int h = 0; h < 2; h++) {
            const int r = wm * 32 + mt * 16 + lm + h * 8;
            tk[mt][h] = stok[r]; vv[mt][h] = (base + r) < cnt;
        }

    const uint32_t* Hs = (const uint32_t*)(dsm + S2_H);
    float c[2][4][4];

    for (int ch = 0; ch < 16; ch++) {
        CPWAIT(0);
        __syncthreads();
#pragma unroll
        for (int mt = 0; mt < 2; mt++)
#pragma unroll
            for (int nt = 0; nt < 4; nt++)
#pragma unroll
                for (int q = 0; q < 4; q++) c[mt][nt][q] = 0.f;

        const float* Bs = (const float*)(dsm + S2_B);
#pragma unroll
        for (int ks = 0; ks < 16; ks++) {
            const int k0 = ks * 8 + lk;
            uint32_t af[2][4], bf[4][2];
#pragma unroll
            for (int mt = 0; mt < 2; mt++) {
                const int r0 = wm * 32 + mt * 16 + lm;
                af[mt][0] = Hs[r0 * 132 + k0];
                af[mt][1] = Hs[(r0 + 8) * 132 + k0];
                af[mt][2] = Hs[r0 * 132 + k0 + 4];
                af[mt][3] = Hs[(r0 + 8) * 132 + k0 + 4];
            }
#pragma unroll
            for (int nt = 0; nt < 4; nt++) {
                const int n0 = wn * 32 + nt * 8 + lm;
                bf[nt][0] = cvt_tf32(Bs[n0 * 132 + k0]);
                bf[nt][1] = cvt_tf32(Bs[n0 * 132 + k0 + 4]);
            }
#pragma unroll
            for (int mt = 0; mt < 2; mt++)
#pragma unroll
                for (int nt = 0; nt < 4; nt++) mma8(c[mt][nt], af[mt], bf[nt]);
        }
        __syncthreads();   // all warps done reading B before overwrite
        if (ch + 1 < 16) { // next B load overlaps the out-store epilogue
            const float* gp = bg + (size_t)(ch + 1) * 128 * R_RANK;
#pragma unroll
            for (int j = 0; j < 16; j++)
                CP16(sb + S2_B + bo + j * 4224u, gp + (size_t)j * 8 * R_RANK);
            CPCOMMIT();
        }
        const int d0 = (nh * 16 + ch) * 128;
#pragma unroll
        for (int mt = 0; mt < 2; mt++)
#pragma unroll
            for (int h = 0; h < 2; h++) {
                if (!vv[mt][h]) continue;
                float* op = out + (size_t)tk[mt][h] * D_DIM + d0 + wn * 32 + lk * 2;
                if (slot == 0) {
#pragma unroll
                    for (int nt = 0; nt < 4; nt++)
                        *(float2*)(op + nt * 8) =
                            make_float2(c[mt][nt][h * 2], c[mt][nt][h * 2 + 1]);
                } else {
#pragma unroll
                    for (int nt = 0; nt < 4; nt++) {
                        float2 o2 = *(const float2*)(op + nt * 8);
                        o2.x += c[mt][nt][h * 2];
                        o2.y += c[mt][nt][h * 2 + 1];
                        *(float2*)(op + nt * 8) = o2;
                    }
                }
            }
    }
}

extern "C" void kernel_launch(void* const* d_in, const int* in_sizes, int n_in,
                              void* d_out, int out_size)
{
    (void)in_sizes; (void)n_in; (void)out_size;
    const float* x  = (const float*)d_in[0];
    const float* Wr = (const float*)d_in[1];
    const float* br = (const float*)d_in[2];
    const float* A  = (const float*)d_in[3];
    const float* B  = (const float*)d_in[4];
    float* out = (float*)d_out;

    cudaFuncSetAttribute(s1_kernel, cudaFuncAttributeMaxDynamicSharedMemorySize, SMEM_S1);
    cudaFuncSetAttribute(s2_kernel, cudaFuncAttributeMaxDynamicSharedMemorySize, SMEM_S2);
    reset_kernel<<<1, 32>>>();
    router_kernel<<<N_TOK / 4, 256>>>(x, Wr, br);
    dim3 g1(N_TOK / MT, E_NUM, 2);
    s1_kernel<<<g1, 256, SMEM_S1>>>(x, A);
    dim3 g2(N_TOK / MT, 2, E_NUM);
    s2_kernel<<<g2, 256, SMEM_S2>>>(B, out, 0);
    s2_kernel<<<g2, 256, SMEM_S2>>>(B, out, 1);
}

// round 15
// speedup vs baseline: 1.2365x; 1.2365x over previous
#include <cuda_runtime.h>
#include <cstdint>
#include <math.h>

#define N_TOK   8192
#define D_DIM   4096
#define E_NUM   8
#define R_RANK  128
#define SCALING 0.25f
#define MT      64

__device__ int   g_cnt[2][E_NUM];
__device__ int   g_tok[2][E_NUM][N_TOK];
__device__ float g_wt [2][E_NUM][N_TOK];
// gate-weighted, tf32-rounded H for every (slot, expert, list-position)
__device__ float g_h[2][E_NUM][N_TOK][R_RANK];   // 64 MB reserved, 8 MB live

// ---- stage-1 smem (KB=32, TRIPLE buffered): X[64][36w] x3 + A[128][36w] x3 ----
#define S1_X(b) ((b) * 9216)
#define S1_A(b) (27648 + (b) * 18432)
#define SMEM_S1 82944
// ---- stage-2 smem (101376 B -> 2 CTAs/SM) ----
#define S2_H    0                          // H [64][132w]
#define S2_B    33792                      // B [128][132w] single buffer
#define SMEM_S2 101376

__device__ __forceinline__ uint32_t smem_u32(const void* p) {
    uint32_t a;
    asm("{ .reg .u64 t; cvta.to.shared.u64 t, %1; cvt.u32.u64 %0, t; }" : "=r"(a) : "l"(p));
    return a;
}
__device__ __forceinline__ uint32_t cvt_tf32(float f) {
    uint32_t r; asm("cvt.rna.tf32.f32 %0, %1;" : "=r"(r) : "f"(f)); return r;
}
#define CP16(sa, gp) asm volatile("cp.async.cg.shared.global [%0], [%1], 16;" :: "r"(sa), "l"(gp))
#define CPCOMMIT()   asm volatile("cp.async.commit_group;" ::: "memory")
#define CPWAIT(n)    asm volatile("cp.async.wait_group %0;" :: "n"(n) : "memory")

__device__ __forceinline__ void mma8(float* c, const uint32_t* a, const uint32_t* b) {
    asm volatile("mma.sync.aligned.m16n8k8.row.col.f32.tf32.tf32.f32 "
        "{%0,%1,%2,%3}, {%4,%5,%6,%7}, {%8,%9}, {%0,%1,%2,%3};"
        : "+f"(c[0]), "+f"(c[1]), "+f"(c[2]), "+f"(c[3])
        : "r"(a[0]), "r"(a[1]), "r"(a[2]), "r"(a[3]), "r"(b[0]), "r"(b[1]));
}

// ---------------- kernels ----------------
__global__ void reset_kernel() {
    if (threadIdx.x < 2 * E_NUM) ((int*)g_cnt)[threadIdx.x] = 0;
}

// Router v4: 4 tokens/block.
__global__ __launch_bounds__(256) void router_kernel(
    const float* __restrict__ x, const float* __restrict__ Wr, const float* __restrict__ br)
{
    const int n0 = blockIdx.x * 4, tid = threadIdx.x;
    const int warp = tid >> 5, lane = tid & 31;
    float acc[4][E_NUM];
#pragma unroll
    for (int t = 0; t < 4; t++)
#pragma unroll
        for (int e = 0; e < E_NUM; e++) acc[t][e] = 0.f;
    for (int d = tid * 4; d < D_DIM; d += 1024) {
        float4 wv[E_NUM];
#pragma unroll
        for (int e = 0; e < E_NUM; e++) wv[e] = *(const float4*)(Wr + (size_t)e * D_DIM + d);
#pragma unroll
        for (int t = 0; t < 4; t++) {
            float4 xv = *(const float4*)(x + (size_t)(n0 + t) * D_DIM + d);
#pragma unroll
            for (int e = 0; e < E_NUM; e++)
                acc[t][e] += xv.x*wv[e].x + xv.y*wv[e].y + xv.z*wv[e].z + xv.w*wv[e].w;
        }
    }
#pragma unroll
    for (int off = 16; off > 0; off >>= 1)
#pragma unroll
        for (int t = 0; t < 4; t++)
#pragma unroll
            for (int e = 0; e < E_NUM; e++)
                acc[t][e] += __shfl_xor_sync(0xffffffffu, acc[t][e], off);
    __shared__ float sm[8][4][E_NUM];
    if (lane == 0)
#pragma unroll
        for (int t = 0; t < 4; t++)
#pragma unroll
            for (int e = 0; e < E_NUM; e++) sm[warp][t][e] = acc[t][e];
    __syncthreads();
    if (tid < 4) {
        const int n = n0 + tid;
        float lg[E_NUM];
#pragma unroll
        for (int e = 0; e < E_NUM; e++) {
            float s = 0.f;
#pragma unroll
            for (int w = 0; w < 8; w++) s += sm[w][tid][e];
            lg[e] = s + br[e];
        }
        int i0 = 0;
#pragma unroll
        for (int e = 1; e < E_NUM; e++) if (lg[e] > lg[i0]) i0 = e;
        int i1 = (i0 == 0) ? 1 : 0;
#pragma unroll
        for (int e = 0; e < E_NUM; e++) if (e != i0 && lg[e] > lg[i1]) i1 = e;
        float e1  = expf(lg[i1] - lg[i0]);
        float inv = SCALING / (1.f + e1);
        int p0 = atomicAdd(&g_cnt[0][i0], 1);
        g_tok[0][i0][p0] = n;  g_wt[0][i0][p0] = inv;
        int p1 = atomicAdd(&g_cnt[1][i1], 1);
        g_tok[1][i1][p1] = n;  g_wt[1][i1][p1] = e1 * inv;
    }
}

// Stage 1 (both slots, 256 active blocks, 2 CTAs/SM, KB=32, triple-buffered,
// ONE barrier per k-tile): H[slot][e][base+r][:] = gate * (X_g @ A_e^T).
__global__ __launch_bounds__(256, 2)
void s1_kernel(const float* __restrict__ x, const float* __restrict__ A)
{
    const int slot = blockIdx.z, e = blockIdx.y;
    const int cnt  = g_cnt[slot][e];
    const int base = blockIdx.x * MT;
    if (base >= cnt) return;

    extern __shared__ char dsm[];
    __shared__ int   stok[MT];
    __shared__ float swt[MT];

    const int tid  = threadIdx.x;
    const int lane = tid & 31, warp = tid >> 5;
    const int wm = warp >> 2, wn = warp & 3;
    const int lm = lane >> 2, lk = lane & 3;

    if (tid < MT) {
        int p = base + tid;
        if (p < cnt) { stok[tid] = g_tok[slot][e][p];    swt[tid] = g_wt[slot][e][p]; }
        else         { stok[tid] = g_tok[slot][e][base]; swt[tid] = 0.f;              }
    }
    __syncthreads();

    const uint32_t sb = smem_u32(dsm);
    // X loader (R13-proven): rows tid>>3 and +32, col16 = tid&7; stride 144 B
    const int xr0 = tid >> 3, xc = tid & 7;
    const float* xg0 = x + (size_t)stok[xr0]      * D_DIM + xc * 4;
    const float* xg1 = x + (size_t)stok[xr0 + 32] * D_DIM + xc * 4;
    const uint32_t xo0 = (uint32_t)xr0 * 144u + (uint32_t)xc * 16u;
    const uint32_t xo1 = (uint32_t)(xr0 + 32) * 144u + (uint32_t)xc * 16u;
    // A loader (R13-proven): 4 rows strided 32, col16 = tid&7
    const float* ag0 = A + ((size_t)e * R_RANK + xr0) * D_DIM + xc * 4;
    const uint32_t ao0 = (uint32_t)xr0 * 144u + (uint32_t)xc * 16u;

    float c[2][4][4];
#pragma unroll
    for (int mt = 0; mt < 2; mt++)
#pragma unroll
        for (int nt = 0; nt < 4; nt++)
#pragma unroll
            for (int q = 0; q < 4; q++) c[mt][nt][q] = 0.f;

#define S1_LOAD(BUF, KT) do {                                                  \
    const int _gk = (KT) * 32;                                                 \
    CP16(sb + S1_X(BUF) + xo0, xg0 + _gk);                                     \
    CP16(sb + S1_X(BUF) + xo1, xg1 + _gk);                                     \
    _Pragma("unroll")                                                          \
    for (int _j = 0; _j < 4; _j++)                                             \
        CP16(sb + S1_A(BUF) + ao0 + _j * 4608u, ag0 + (size_t)_j * 32 * D_DIM + _gk); \
    CPCOMMIT();                                                                \
} while (0)

    S1_LOAD(0, 0);
    S1_LOAD(1, 1);

    int buf = 0;
    for (int kt = 0; kt < 128; kt++) {
        if (kt < 127) CPWAIT(1); else CPWAIT(0);   // tile kt resident
        __syncthreads();                            // all CTA sees it; mma kt-1 done by all
        if (kt + 2 < 128) {
            int nb = buf + 2; if (nb >= 3) nb -= 3;
            S1_LOAD(nb, kt + 2);                    // safe: untouched by mma kt, kt+1
        }
        const float* Xs = (const float*)(dsm + S1_X(buf));
        const float* As = (const float*)(dsm + S1_A(buf));
#pragma unroll
        for (int ks = 0; ks < 4; ks++) {
            const int k0 = ks * 8 + lk;
            uint32_t af[2][4], bf[4][2];
#pragma unroll
            for (int mt = 0; mt < 2; mt++) {
                const int r0 = wm * 32 + mt * 16 + lm;
                af[mt][0] = cvt_tf32(Xs[r0 * 36 + k0]);
                af[mt][1] = cvt_tf32(Xs[(r0 + 8) * 36 + k0]);
                af[mt][2] = cvt_tf32(Xs[r0 * 36 + k0 + 4]);
                af[mt][3] = cvt_tf32(Xs[(r0 + 8) * 36 + k0 + 4]);
            }
#pragma unroll
            for (int nt = 0; nt < 4; nt++) {
                const int n0 = wn * 32 + nt * 8 + lm;
                bf[nt][0] = cvt_tf32(As[n0 * 36 + k0]);
                bf[nt][1] = cvt_tf32(As[n0 * 36 + k0 + 4]);
            }
#pragma unroll
            for (int mt = 0; mt < 2; mt++)
#pragma unroll
                for (int nt = 0; nt < 4; nt++) mma8(c[mt][nt], af[mt], bf[nt]);
        }
        if (++buf == 3) buf = 0;
    }

    // H epilogue: gate-weight + tf32 -> gmem (L2-resident, 8 MB live)
#pragma unroll
    for (int mt = 0; mt < 2; mt++)
#pragma unroll
        for (int h = 0; h < 2; h++) {
            const int r = wm * 32 + mt * 16 + lm + h * 8;
            const float w = swt[r];
            uint32_t* hp = (uint32_t*)&g_h[slot][e][base + r][0];
#pragma unroll
            for (int nt = 0; nt < 4; nt++) {
                const int col = wn * 32 + nt * 8 + lk * 2;
                uint2 v;
                v.x = cvt_tf32(c[mt][nt][h * 2]     * w);
                v.y = cvt_tf32(c[mt][nt][h * 2 + 1] * w);
                *(uint2*)&hp[col] = v;
            }
        }
}

// Stage 2 (R13 verbatim): out (+)= H @ B_e^T. Grid (tiles, nhalf, expert).
__global__ __launch_bounds__(256, 2)
void s2_kernel(const float* __restrict__ B, float* __restrict__ out, int slot)
{
    const int e    = blockIdx.z;
    const int nh   = blockIdx.y;
    const int cnt  = g_cnt[slot][e];
    const int base = blockIdx.x * MT;
    if (base >= cnt) return;

    extern __shared__ char dsm[];
    __shared__ int stok[MT];

    const int tid  = threadIdx.x;
    const int lane = tid & 31, warp = tid >> 5;
    const int wm = warp >> 2, wn = warp & 3;
    const int lm = lane >> 2, lk = lane & 3;

    if (tid < MT) {
        int p = base + tid;
        stok[tid] = (p < cnt) ? g_tok[slot][e][p] : g_tok[slot][e][base];
    }
    __syncthreads();

    const uint32_t sb = smem_u32(dsm);

    const int hr = tid >> 2, hq = tid & 3;
    const float* hg = &g_h[slot][e][base + hr][hq * 32];
    const uint32_t ho = (uint32_t)hr * 528u + (uint32_t)hq * 128u;
#pragma unroll
    for (int j = 0; j < 8; j++)
        CP16(sb + S2_H + ho + j * 16u, hg + j * 4);
    CPCOMMIT();

    const float* bg = B + (size_t)e * D_DIM * R_RANK
                        + ((size_t)nh * 16 * 128 + warp) * R_RANK + lane * 4;
    const uint32_t bo = (uint32_t)warp * 528u + (uint32_t)lane * 16u;
#pragma unroll
    for (int j = 0; j < 16; j++)
        CP16(sb + S2_B + bo + j * 4224u, bg + (size_t)j * 8 * R_RANK);
    CPCOMMIT();

    int tk[2][2]; bool vv[2][2];
#pragma unroll
    for (int mt = 0; mt < 2; mt++)
#pragma unroll
        for (int h = 0; h < 2; h++) {
            const int r = wm * 32 + mt * 16 + lm + h * 8;
            tk[mt][h] = stok[r]; vv[mt][h] = (base + r) < cnt;
        }

    const uint32_t* Hs = (const uint32_t*)(dsm + S2_H);
    float c[2][4][4];

    for (int ch = 0; ch < 16; ch++) {
        CPWAIT(0);
        __syncthreads();
#pragma unroll
        for (int mt = 0; mt < 2; mt++)
#pragma unroll
            for (int nt = 0; nt < 4; nt++)
#pragma unroll
                for (int q = 0; q < 4; q++) c[mt][nt][q] = 0.f;

        const float* Bs = (const float*)(dsm + S2_B);
#pragma unroll
        for (int ks = 0; ks < 16; ks++) {
            const int k0 = ks * 8 + lk;
            uint32_t af[2][4], bf[4][2];
#pragma unroll
            for (int mt = 0; mt < 2; mt++) {
                const int r0 = wm * 32 + mt * 16 + lm;
                af[mt][0] = Hs[r0 * 132 + k0];
                af[mt][1] = Hs[(r0 + 8) * 132 + k0];
                af[mt][2] = Hs[r0 * 132 + k0 + 4];
                af[mt][3] = Hs[(r0 + 8) * 132 + k0 + 4];
            }
#pragma unroll
            for (int nt = 0; nt < 4; nt++) {
                const int n0 = wn * 32 + nt * 8 + lm;
                bf[nt][0] = cvt_tf32(Bs[n0 * 132 + k0]);
                bf[nt][1] = cvt_tf32(Bs[n0 * 132 + k0 + 4]);
            }
#pragma unroll
            for (int mt = 0; mt < 2; mt++)
#pragma unroll
                for (int nt = 0; nt < 4; nt++) mma8(c[mt][nt], af[mt], bf[nt]);
        }
        __syncthreads();
        if (ch + 1 < 16) {
            const float* gp = bg + (size_t)(ch + 1) * 128 * R_RANK;
#pragma unroll
            for (int j = 0; j < 16; j++)
                CP16(sb + S2_B + bo + j * 4224u, gp + (size_t)j * 8 * R_RANK);
            CPCOMMIT();
        }
        const int d0 = (nh * 16 + ch) * 128;
#pragma unroll
        for (int mt = 0; mt < 2; mt++)
#pragma unroll
            for (int h = 0; h < 2; h++) {
                if (!vv[mt][h]) continue;
                float* op = out + (size_t)tk[mt][h] * D_DIM + d0 + wn * 32 + lk * 2;
                if (slot == 0) {
#pragma unroll
                    for (int nt = 0; nt < 4; nt++)
                        *(float2*)(op + nt * 8) =
                            make_float2(c[mt][nt][h * 2], c[mt][nt][h * 2 + 1]);
                } else {
#pragma unroll
                    for (int nt = 0; nt < 4; nt++) {
                        float2 o2 = *(const float2*)(op + nt * 8);
                        o2.x += c[mt][nt][h * 2];
                        o2.y += c[mt][nt][h * 2 + 1];
                        *(float2*)(op + nt * 8) = o2;
                    }
                }
            }
    }
}

extern "C" void kernel_launch(void* const* d_in, const int* in_sizes, int n_in,
                              void* d_out, int out_size)
{
    (void)in_sizes; (void)n_in; (void)out_size;
    const float* x  = (const float*)d_in[0];
    const float* Wr = (const float*)d_in[1];
    const float* br = (const float*)d_in[2];
    const float* A  = (const float*)d_in[3];
    const float* B  = (const float*)d_in[4];
    float* out = (float*)d_out;

    cudaFuncSetAttribute(s1_kernel, cudaFuncAttributeMaxDynamicSharedMemorySize, SMEM_S1);
    cudaFuncSetAttribute(s2_kernel, cudaFuncAttributeMaxDynamicSharedMemorySize, SMEM_S2);
    reset_kernel<<<1, 32>>>();
    router_kernel<<<N_TOK / 4, 256>>>(x, Wr, br);
    dim3 g1(N_TOK / MT, E_NUM, 2);
    s1_kernel<<<g1, 256, SMEM_S1>>>(x, A);
    dim3 g2(N_TOK / MT, 2, E_NUM);
    s2_kernel<<<g2, 256, SMEM_S2>>>(B, out, 0);
    s2_kernel<<<g2, 256, SMEM_S2>>>(B, out, 1);
}

// round 16
// speedup vs baseline: 1.3683x; 1.1065x over previous
#include <cuda_runtime.h>
#include <cstdint>
#include <math.h>

#define N_TOK   8192
#define D_DIM   4096
#define E_NUM   8
#define R_RANK  128
#define SCALING 0.25f
#define MT      64

__device__ int   g_cnt[2][E_NUM];
__device__ int   g_tok[2][E_NUM][N_TOK];
__device__ float g_wt [2][E_NUM][N_TOK];
// gate-weighted, tf32, k-pair-permuted H rows (8-group order {0,4,1,5,2,6,3,7})
__device__ float g_h[2][E_NUM][N_TOK][R_RANK];   // 64 MB reserved, 8 MB live
// tf32-preconverted + k-pair-permuted weights
__device__ float g_at[(size_t)E_NUM * R_RANK * D_DIM];   // 16 MB
__device__ float g_bt[(size_t)E_NUM * D_DIM * R_RANK];   // 16 MB

// ---- stage-1 smem: X[64][36w] x2 + A[128][40w] x2 = 59392 B ----
#define S1_X(b) ((b) * 9216)
#define S1_A(b) (18432 + (b) * 20480)
#define SMEM_S1 59392
// ---- stage-2 smem: H[64][136w] + B[128][136w] = 104448 B (2 CTAs/SM) ----
#define S2_H    0
#define S2_B    34816
#define SMEM_S2 104448

__device__ __forceinline__ uint32_t smem_u32(const void* p) {
    uint32_t a;
    asm("{ .reg .u64 t; cvta.to.shared.u64 t, %1; cvt.u32.u64 %0, t; }" : "=r"(a) : "l"(p));
    return a;
}
__device__ __forceinline__ uint32_t cvt_tf32(float f) {
    uint32_t r; asm("cvt.rna.tf32.f32 %0, %1;" : "=r"(r) : "f"(f)); return r;
}
#define CP16(sa, gp) asm volatile("cp.async.cg.shared.global [%0], [%1], 16;" :: "r"(sa), "l"(gp))
#define CPCOMMIT()   asm volatile("cp.async.commit_group;" ::: "memory")
#define CPWAIT(n)    asm volatile("cp.async.wait_group %0;" :: "n"(n) : "memory")

__device__ __forceinline__ void mma8(float* c, const uint32_t* a, const uint32_t* b) {
    asm volatile("mma.sync.aligned.m16n8k8.row.col.f32.tf32.tf32.f32 "
        "{%0,%1,%2,%3}, {%4,%5,%6,%7}, {%8,%9}, {%0,%1,%2,%3};"
        : "+f"(c[0]), "+f"(c[1]), "+f"(c[2]), "+f"(c[3])
        : "r"(a[0]), "r"(a[1]), "r"(a[2]), "r"(a[3]), "r"(b[0]), "r"(b[1]));
}

// ---------------- kernels ----------------
__global__ void reset_kernel() {
    if (threadIdx.x < 2 * E_NUM) ((int*)g_cnt)[threadIdx.x] = 0;
}

// Convert + k-pair permute A and B (R12-proven): one thread per 8-group.
__global__ __launch_bounds__(256) void cvt_wt(const float4* __restrict__ A,
                                              const float4* __restrict__ B)
{
    size_t g = (size_t)blockIdx.x * blockDim.x + threadIdx.x;
    const size_t ng = (size_t)E_NUM * R_RANK * D_DIM / 8;
    if (g >= ng) return;
    float4 a0 = A[g*2], a1 = A[g*2+1];
    ((uint4*)g_at)[g*2]   = make_uint4(cvt_tf32(a0.x), cvt_tf32(a1.x), cvt_tf32(a0.y), cvt_tf32(a1.y));
    ((uint4*)g_at)[g*2+1] = make_uint4(cvt_tf32(a0.z), cvt_tf32(a1.z), cvt_tf32(a0.w), cvt_tf32(a1.w));
    float4 b0 = B[g*2], b1 = B[g*2+1];
    ((uint4*)g_bt)[g*2]   = make_uint4(cvt_tf32(b0.x), cvt_tf32(b1.x), cvt_tf32(b0.y), cvt_tf32(b1.y));
    ((uint4*)g_bt)[g*2+1] = make_uint4(cvt_tf32(b0.z), cvt_tf32(b1.z), cvt_tf32(b0.w), cvt_tf32(b1.w));
}

// Router v4: 4 tokens/block.
__global__ __launch_bounds__(256) void router_kernel(
    const float* __restrict__ x, const float* __restrict__ Wr, const float* __restrict__ br)
{
    const int n0 = blockIdx.x * 4, tid = threadIdx.x;
    const int warp = tid >> 5, lane = tid & 31;
    float acc[4][E_NUM];
#pragma unroll
    for (int t = 0; t < 4; t++)
#pragma unroll
        for (int e = 0; e < E_NUM; e++) acc[t][e] = 0.f;
    for (int d = tid * 4; d < D_DIM; d += 1024) {
        float4 wv[E_NUM];
#pragma unroll
        for (int e = 0; e < E_NUM; e++) wv[e] = *(const float4*)(Wr + (size_t)e * D_DIM + d);
#pragma unroll
        for (int t = 0; t < 4; t++) {
            float4 xv = *(const float4*)(x + (size_t)(n0 + t) * D_DIM + d);
#pragma unroll
            for (int e = 0; e < E_NUM; e++)
                acc[t][e] += xv.x*wv[e].x + xv.y*wv[e].y + xv.z*wv[e].z + xv.w*wv[e].w;
        }
    }
#pragma unroll
    for (int off = 16; off > 0; off >>= 1)
#pragma unroll
        for (int t = 0; t < 4; t++)
#pragma unroll
            for (int e = 0; e < E_NUM; e++)
                acc[t][e] += __shfl_xor_sync(0xffffffffu, acc[t][e], off);
    __shared__ float sm[8][4][E_NUM];
    if (lane == 0)
#pragma unroll
        for (int t = 0; t < 4; t++)
#pragma unroll
            for (int e = 0; e < E_NUM; e++) sm[warp][t][e] = acc[t][e];
    __syncthreads();
    if (tid < 4) {
        const int n = n0 + tid;
        float lg[E_NUM];
#pragma unroll
        for (int e = 0; e < E_NUM; e++) {
            float s = 0.f;
#pragma unroll
            for (int w = 0; w < 8; w++) s += sm[w][tid][e];
            lg[e] = s + br[e];
        }
        int i0 = 0;
#pragma unroll
        for (int e = 1; e < E_NUM; e++) if (lg[e] > lg[i0]) i0 = e;
        int i1 = (i0 == 0) ? 1 : 0;
#pragma unroll
        for (int e = 0; e < E_NUM; e++) if (e != i0 && lg[e] > lg[i1]) i1 = e;
        float e1  = expf(lg[i1] - lg[i0]);
        float inv = SCALING / (1.f + e1);
        int p0 = atomicAdd(&g_cnt[0][i0], 1);
        g_tok[0][i0][p0] = n;  g_wt[0][i0][p0] = inv;
        int p1 = atomicAdd(&g_cnt[1][i1], 1);
        g_tok[1][i1][p1] = n;  g_wt[1][i1][p1] = e1 * inv;
    }
}

// Stage 1: H = gate * (X_g @ A_e^T); A k-pair (LDS.64 bf), X scalar+cvt (R13).
__global__ __launch_bounds__(256, 2)
void s1_kernel(const float* __restrict__ x)
{
    const int slot = blockIdx.z, e = blockIdx.y;
    const int cnt  = g_cnt[slot][e];
    const int base = blockIdx.x * MT;
    if (base >= cnt) return;

    extern __shared__ char dsm[];
    __shared__ int   stok[MT];
    __shared__ float swt[MT];

    const int tid  = threadIdx.x;
    const int lane = tid & 31, warp = tid >> 5;
    const int wm = warp >> 2, wn = warp & 3;
    const int lm = lane >> 2, lk = lane & 3;

    if (tid < MT) {
        int p = base + tid;
        if (p < cnt) { stok[tid] = g_tok[slot][e][p];    swt[tid] = g_wt[slot][e][p]; }
        else         { stok[tid] = g_tok[slot][e][base]; swt[tid] = 0.f;              }
    }
    __syncthreads();

    const uint32_t sb = smem_u32(dsm);
    // X loader (R13): rows tid>>3 and +32, col16 = tid&7; stride 144 B
    const int xr0 = tid >> 3, xc = tid & 7;
    const float* xg0 = x + (size_t)stok[xr0]      * D_DIM + xc * 4;
    const float* xg1 = x + (size_t)stok[xr0 + 32] * D_DIM + xc * 4;
    const uint32_t xo0 = (uint32_t)xr0 * 144u + (uint32_t)xc * 16u;
    const uint32_t xo1 = (uint32_t)(xr0 + 32) * 144u + (uint32_t)xc * 16u;
    // A loader from g_at (permuted): same 4-rows pattern, smem stride 160 B
    const float* ag0 = g_at + ((size_t)e * R_RANK + xr0) * D_DIM + xc * 4;
    const uint32_t ao0 = (uint32_t)xr0 * 160u + (uint32_t)xc * 16u;

    float c[2][4][4];
#pragma unroll
    for (int mt = 0; mt < 2; mt++)
#pragma unroll
        for (int nt = 0; nt < 4; nt++)
#pragma unroll
            for (int q = 0; q < 4; q++) c[mt][nt][q] = 0.f;

    {
        CP16(sb + S1_X(0) + xo0, xg0);
        CP16(sb + S1_X(0) + xo1, xg1);
#pragma unroll
        for (int j = 0; j < 4; j++)
            CP16(sb + S1_A(0) + ao0 + j * 5120u, ag0 + (size_t)j * 32 * D_DIM);
        CPCOMMIT();
    }
    for (int kt = 0; kt < 128; kt++) {
        if (kt + 1 < 128) {
            const int b = (kt + 1) & 1, gk = (kt + 1) * 32;
            CP16(sb + S1_X(b) + xo0, xg0 + gk);
            CP16(sb + S1_X(b) + xo1, xg1 + gk);
#pragma unroll
            for (int j = 0; j < 4; j++)
                CP16(sb + S1_A(b) + ao0 + j * 5120u, ag0 + (size_t)j * 32 * D_DIM + gk);
            CPCOMMIT();
            CPWAIT(1);
        } else {
            CPWAIT(0);
        }
        __syncthreads();
        const float* Xs = (const float*)(dsm + S1_X(kt & 1));
        const uint2* A2 = (const uint2*)(dsm + S1_A(kt & 1));   // stride 20 uint2
#pragma unroll
        for (int ks = 0; ks < 4; ks++) {
            const int k0 = ks * 8 + lk;
            const int kw = ks * 4 + lk;
            uint32_t af[2][4], bf[4][2];
#pragma unroll
            for (int mt = 0; mt < 2; mt++) {
                const int r0 = wm * 32 + mt * 16 + lm;
                af[mt][0] = cvt_tf32(Xs[r0 * 36 + k0]);
                af[mt][1] = cvt_tf32(Xs[(r0 + 8) * 36 + k0]);
                af[mt][2] = cvt_tf32(Xs[r0 * 36 + k0 + 4]);
                af[mt][3] = cvt_tf32(Xs[(r0 + 8) * 36 + k0 + 4]);
            }
#pragma unroll
            for (int nt = 0; nt < 4; nt++) {
                uint2 v = A2[(wn * 32 + nt * 8 + lm) * 20 + kw];
                bf[nt][0] = v.x; bf[nt][1] = v.y;
            }
#pragma unroll
            for (int mt = 0; mt < 2; mt++)
#pragma unroll
                for (int nt = 0; nt < 4; nt++) mma8(c[mt][nt], af[mt], bf[nt]);
        }
        __syncthreads();
    }

    // H epilogue: gate-weight + tf32 -> gmem in k-pair permuted order
#pragma unroll
    for (int mt = 0; mt < 2; mt++)
#pragma unroll
        for (int h = 0; h < 2; h++) {
            const int r = wm * 32 + mt * 16 + lm + h * 8;
            const float w = swt[r];
            uint32_t* hp = (uint32_t*)&g_h[slot][e][base + r][0];
            const int o  = lk * 2;
            const int w0 = 2 * (o & 3) + (o >> 2);
            const int w1 = 2 * ((o + 1) & 3) + ((o + 1) >> 2);
#pragma unroll
            for (int nt = 0; nt < 4; nt++) {
                const int gb = (wn * 4 + nt) * 8;
                hp[gb + w0] = cvt_tf32(c[mt][nt][h * 2]     * w);
                hp[gb + w1] = cvt_tf32(c[mt][nt][h * 2 + 1] * w);
            }
        }
}

// Stage 2: out (+)= H @ B_e^T; H and B k-pair (all-LDS.64, zero cvts in loop).
__global__ __launch_bounds__(256, 2)
void s2_kernel(float* __restrict__ out, int slot)
{
    const int e    = blockIdx.z;
    const int nh   = blockIdx.y;
    const int cnt  = g_cnt[slot][e];
    const int base = blockIdx.x * MT;
    if (base >= cnt) return;

    extern __shared__ char dsm[];
    __shared__ int stok[MT];

    const int tid  = threadIdx.x;
    const int lane = tid & 31, warp = tid >> 5;
    const int wm = warp >> 2, wn = warp & 3;
    const int lm = lane >> 2, lk = lane & 3;

    if (tid < MT) {
        int p = base + tid;
        stok[tid] = (p < cnt) ? g_tok[slot][e][p] : g_tok[slot][e][base];
    }
    __syncthreads();

    const uint32_t sb = smem_u32(dsm);

    // H load: 8 CP16/thread; row = tid>>2; smem stride 544 B
    const int hr = tid >> 2, hq = tid & 3;
    const float* hg = &g_h[slot][e][base + hr][hq * 32];
    const uint32_t ho = (uint32_t)hr * 544u + (uint32_t)hq * 128u;
#pragma unroll
    for (int j = 0; j < 8; j++)
        CP16(sb + S2_H + ho + j * 16u, hg + j * 4);
    CPCOMMIT();

    // B loader from g_bt (permuted): rows warp + 8j; smem stride 544 B
    const float* bg = g_bt + (size_t)e * D_DIM * R_RANK
                        + ((size_t)nh * 16 * 128 + warp) * R_RANK + lane * 4;
    const uint32_t bo = (uint32_t)warp * 544u + (uint32_t)lane * 16u;
#pragma unroll
    for (int j = 0; j < 16; j++)
        CP16(sb + S2_B + bo + j * 4352u, bg + (size_t)j * 8 * R_RANK);
    CPCOMMIT();

    int tk[2][2]; bool vv[2][2];
#pragma unroll
    for (int mt = 0; mt < 2; mt++)
#pragma unroll
        for (int h = 0; h < 2; h++) {
            const int r = wm * 32 + mt * 16 + lm + h * 8;
            tk[mt][h] = stok[r]; vv[mt][h] = (base + r) < cnt;
        }

    const uint2* H2 = (const uint2*)(dsm + S2_H);   // stride 68 uint2
    float c[2][4][4];

    for (int ch = 0; ch < 16; ch++) {
        CPWAIT(0);
        __syncthreads();
#pragma unroll
        for (int mt = 0; mt < 2; mt++)
#pragma unroll
            for (int nt = 0; nt < 4; nt++)
#pragma unroll
                for (int q = 0; q < 4; q++) c[mt][nt][q] = 0.f;

        const uint2* B2 = (const uint2*)(dsm + S2_B);   // stride 68 uint2
#pragma unroll
        for (int ks = 0; ks < 16; ks++) {
            const int kw = ks * 4 + lk;
            uint32_t af[2][4], bf[4][2];
#pragma unroll
            for (int mt = 0; mt < 2; mt++) {
                const int r0 = wm * 32 + mt * 16 + lm;
                uint2 lo = H2[r0 * 68 + kw];
                uint2 hi = H2[(r0 + 8) * 68 + kw];
                af[mt][0] = lo.x; af[mt][1] = hi.x; af[mt][2] = lo.y; af[mt][3] = hi.y;
            }
#pragma unroll
            for (int nt = 0; nt < 4; nt++) {
                uint2 v = B2[(wn * 32 + nt * 8 + lm) * 68 + kw];
                bf[nt][0] = v.x; bf[nt][1] = v.y;
            }
#pragma unroll
            for (int mt = 0; mt < 2; mt++)
#pragma unroll
                for (int nt = 0; nt < 4; nt++) mma8(c[mt][nt], af[mt], bf[nt]);
        }
        __syncthreads();
        if (ch + 1 < 16) {
            const float* gp = bg + (size_t)(ch + 1) * 128 * R_RANK;
#pragma unroll
            for (int j = 0; j < 16; j++)
                CP16(sb + S2_B + bo + j * 4352u, gp + (size_t)j * 8 * R_RANK);
            CPCOMMIT();
        }
        const int d0 = (nh * 16 + ch) * 128;
#pragma unroll
        for (int mt = 0; mt < 2; mt++)
#pragma unroll
            for (int h = 0; h < 2; h++) {
                if (!vv[mt][h]) continue;
                float* op = out + (size_t)tk[mt][h] * D_DIM + d0 + wn * 32 + lk * 2;
                if (slot == 0) {
#pragma unroll
                    for (int nt = 0; nt < 4; nt++)
                        *(float2*)(op + nt * 8) =
                            make_float2(c[mt][nt][h * 2], c[mt][nt][h * 2 + 1]);
                } else {
#pragma unroll
                    for (int nt = 0; nt < 4; nt++) {
                        float2 o2 = *(const float2*)(op + nt * 8);
                        o2.x += c[mt][nt][h * 2];
                        o2.y += c[mt][nt][h * 2 + 1];
                        *(float2*)(op + nt * 8) = o2;
                    }
                }
            }
    }
}

extern "C" void kernel_launch(void* const* d_in, const int* in_sizes, int n_in,
                              void* d_out, int out_size)
{
    (void)in_sizes; (void)n_in; (void)out_size;
    const float* x  = (const float*)d_in[0];
    const float* Wr = (const float*)d_in[1];
    const float* br = (const float*)d_in[2];
    const float* A  = (const float*)d_in[3];
    const float* B  = (const float*)d_in[4];
    float* out = (float*)d_out;

    cudaFuncSetAttribute(s1_kernel, cudaFuncAttributeMaxDynamicSharedMemorySize, SMEM_S1);
    cudaFuncSetAttribute(s2_kernel, cudaFuncAttributeMaxDynamicSharedMemorySize, SMEM_S2);
    reset_kernel<<<1, 32>>>();
    cvt_wt<<<(int)(((size_t)E_NUM * R_RANK * D_DIM / 8 + 255) / 256), 256>>>(
        (const float4*)A, (const float4*)B);
    router_kernel<<<N_TOK / 4, 256>>>(x, Wr, br);
    dim3 g1(N_TOK / MT, E_NUM, 2);
    s1_kernel<<<g1, 256, SMEM_S1>>>(x);
    dim3 g2(N_TOK / MT, 2, E_NUM);
    s2_kernel<<<g2, 256, SMEM_S2>>>(out, 0);
    s2_kernel<<<g2, 256, SMEM_S2>>>(out, 1);
}